// round 11
// baseline (speedup 1.0000x reference)
#include <cuda_runtime.h>
#include <cuda_bf16.h>
#include <cstddef>
#include <cstdint>
#include <math_constants.h>

constexpr int N     = 100000;
constexpr int E_IN  = 1600000;
constexpr int HC    = 128;   // H*C, also F_IN
constexpr float SLOPE = 0.2f;   // leaky(v) = 0.6v + 0.4|v|

// ---------------- scratch ----------------
__device__ float g_xl[(size_t)N * HC];
__device__ float g_xr[(size_t)N * HC];
__device__ float g_h1[(size_t)N * HC];
__device__ float g_h2[(size_t)N * HC];
__device__ float g_cl[(size_t)N * 4];    // per-node per-head dot(xl, att)
__device__ int   g_deg[N];
__device__ int   g_cursor[N];
__device__ int   g_rowptr[N + 1];
__device__ int   g_col[E_IN];
// W transposed + bf16 hi/lo split: rows 0-127 = Wl^T, 128-255 = Wr^T (n-major, k contiguous)
__device__ uint4 g_BT_hi[256 * 128 / 8];
__device__ uint4 g_BT_lo[256 * 128 / 8];

__device__ __forceinline__ uint32_t smem_u32(const void* p) {
    uint32_t a;
    asm("{ .reg .u64 t; cvta.to.shared.u64 t, %1; cvt.u32.u64 %0, t; }" : "=r"(a) : "l"(p));
    return a;
}
__device__ __forceinline__ unsigned pkbf(__nv_bfloat16 a, __nv_bfloat16 b) {
    __nv_bfloat162 t(a, b);
    return *reinterpret_cast<unsigned*>(&t);
}
__device__ __forceinline__ void ldsm_x4(uint32_t& r0, uint32_t& r1, uint32_t& r2, uint32_t& r3,
                                        uint32_t addr) {
    asm volatile("ldmatrix.sync.aligned.m8n8.x4.shared.b16 {%0,%1,%2,%3}, [%4];"
                 : "=r"(r0), "=r"(r1), "=r"(r2), "=r"(r3) : "r"(addr));
}
__device__ __forceinline__ void mma_bf16(float* c, uint32_t a0, uint32_t a1, uint32_t a2,
                                         uint32_t a3, uint32_t b0, uint32_t b1) {
    asm volatile("mma.sync.aligned.m16n8k16.row.col.f32.bf16.bf16.f32 "
                 "{%0,%1,%2,%3}, {%4,%5,%6,%7}, {%8,%9}, {%0,%1,%2,%3};"
                 : "+f"(c[0]), "+f"(c[1]), "+f"(c[2]), "+f"(c[3])
                 : "r"(a0), "r"(a1), "r"(a2), "r"(a3), "r"(b0), "r"(b1));
}

// ================= CSR build (once per launch) =================
__global__ void zero_deg() {
    int i = blockIdx.x * blockDim.x + threadIdx.x;
    if (i < N) g_deg[i] = 0;
}
__global__ void hist_dst(const int* __restrict__ dst) {
    int e = blockIdx.x * blockDim.x + threadIdx.x;
    if (e < E_IN) atomicAdd(&g_deg[dst[e]], 1);
}
__global__ void __launch_bounds__(1024) scan_deg() {
    __shared__ int sums[1024];
    const int CH = (N + 1023) / 1024;
    int t = threadIdx.x;
    int start = t * CH;
    int end   = start + CH < N ? start + CH : N;
    int s = 0;
    for (int i = start; i < end; i++) s += g_deg[i];
    sums[t] = s;
    __syncthreads();
    #pragma unroll
    for (int o = 1; o < 1024; o <<= 1) {
        int v = (t >= o) ? sums[t - o] : 0;
        __syncthreads();
        sums[t] += v;
        __syncthreads();
    }
    int run = sums[t] - s;
    for (int i = start; i < end; i++) {
        g_rowptr[i] = run;
        g_cursor[i] = run;
        run += g_deg[i];
    }
    if (t == 1023) g_rowptr[N] = E_IN;
}
__global__ void scatter_csr(const int* __restrict__ src, const int* __restrict__ dst) {
    int e = blockIdx.x * blockDim.x + threadIdx.x;
    if (e >= E_IN) return;
    int pos = atomicAdd(&g_cursor[dst[e]], 1);
    g_col[pos] = src[e];
}

// ================= W prep: transpose + bf16 hi/lo split (per layer) =================
__global__ void wprep(const float* __restrict__ Wl, const float* __restrict__ Wr) {
    __shared__ float t[32][33];
    const float* W = blockIdx.z ? Wr : Wl;
    int k0 = blockIdx.x * 32, n0 = blockIdx.y * 32;
    int tx = threadIdx.x, ty = threadIdx.y;
    t[ty][tx] = W[(k0 + ty) * HC + n0 + tx];
    __syncthreads();
    float v = t[tx][ty];
    __nv_bfloat16 h = __float2bfloat16_rn(v);
    float r = v - __bfloat162float(h);
    __nv_bfloat16 l = __float2bfloat16_rn(r);
    int n = n0 + ty + (int)blockIdx.z * 128;
    int k = k0 + tx;
    reinterpret_cast<__nv_bfloat16*>(g_BT_hi)[n * 128 + k] = h;
    reinterpret_cast<__nv_bfloat16*>(g_BT_lo)[n * 128 + k] = l;
}

// ================= mma.sync bf16 GEMM, 3-term split, both sides fused (R6 config) =================
// CTA: 256 thr = 2(m) x 4(n) warps; tile M64 x N256 (N 0-127 -> xl, 128-255 -> xr), K=128.
constexpr int APAD = 136;                          // bf16 elems per padded row (272 B)
constexpr int SM_A_HI = 0;
constexpr int SM_A_LO = SM_A_HI + 64 * APAD * 2;   // 17408
constexpr int SM_B_HI = SM_A_LO + 64 * APAD * 2;   // 34816
constexpr int SM_B_LO = SM_B_HI + 256 * APAD * 2;  // 104448
constexpr int SM_GEMM_TOTAL = SM_B_LO + 256 * APAD * 2;  // 174080 B

__global__ void __launch_bounds__(256, 1) mma_gemm(const float* __restrict__ X) {
    extern __shared__ char smem[];
    const uint32_t sb = smem_u32(smem);
    const int tid  = threadIdx.x;
    const int wid  = tid >> 5;
    const int lane = tid & 31;
    const int row0 = blockIdx.x * 64;

    // ---- stage A: 64 rows x 128 cols fp32 -> bf16 hi/lo (ONCE for both sides) ----
    const float4* X4 = reinterpret_cast<const float4*>(X);
    #pragma unroll
    for (int it = 0; it < 8; it++) {
        int idx = it * 256 + tid;           // 2048 float4 slots
        int r   = idx >> 5;
        int c4  = idx & 31;
        int g   = row0 + r;
        float4 f = (g < N) ? X4[(size_t)g * 32 + c4] : make_float4(0.f, 0.f, 0.f, 0.f);
        float e[4] = {f.x, f.y, f.z, f.w};
        __nv_bfloat16 h[4], l[4];
        #pragma unroll
        for (int i = 0; i < 4; i++) {
            h[i] = __float2bfloat16_rn(e[i]);
            l[i] = __float2bfloat16_rn(e[i] - __bfloat162float(h[i]));
        }
        uint2 hv = make_uint2(pkbf(h[0], h[1]), pkbf(h[2], h[3]));
        uint2 lv = make_uint2(pkbf(l[0], l[1]), pkbf(l[2], l[3]));
        uint32_t off = (uint32_t)(r * (APAD * 2) + c4 * 8);
        *reinterpret_cast<uint2*>(smem + SM_A_HI + off) = hv;
        *reinterpret_cast<uint2*>(smem + SM_A_LO + off) = lv;
    }
    // ---- stage B: 256 rows(n = [Wl^T; Wr^T]) x 128 cols(k) bf16 ----
    #pragma unroll
    for (int it = 0; it < 16; it++) {
        int idx = it * 256 + tid;           // 4096 uint4 slots
        int r   = idx >> 4;
        int q   = idx & 15;
        uint4 hv = g_BT_hi[r * 16 + q];
        uint4 lv = g_BT_lo[r * 16 + q];
        uint32_t off = (uint32_t)(r * (APAD * 2) + q * 16);
        *reinterpret_cast<uint4*>(smem + SM_B_HI + off) = hv;
        *reinterpret_cast<uint4*>(smem + SM_B_LO + off) = lv;
    }
    __syncthreads();

    const int wm = wid & 1;      // m-warp 0..1 -> rows wm*32 (two m16 tiles)
    const int wn = wid >> 1;     // n-warp 0..3 -> cols wn*64

    float c[2][8][4];
    #pragma unroll
    for (int mt = 0; mt < 2; mt++)
        #pragma unroll
        for (int t = 0; t < 8; t++)
            #pragma unroll
            for (int i = 0; i < 4; i++) c[mt][t][i] = 0.f;

    const uint32_t a_rofs = (uint32_t)(lane & 15);
    const uint32_t a_cofs = (uint32_t)((lane >> 4) * 16);          // bytes
    const uint32_t b_rofs = (uint32_t)((lane & 7) + ((lane & 16) >> 1));
    const uint32_t b_cofs = (uint32_t)(((lane >> 3) & 1) * 16);    // bytes

    #pragma unroll
    for (int term = 0; term < 3; term++) {
        const uint32_t abase = sb + ((term == 2) ? SM_A_LO : SM_A_HI);
        const uint32_t bbase = sb + ((term == 1) ? SM_B_LO : SM_B_HI);
        #pragma unroll
        for (int k16 = 0; k16 < 8; k16++) {
            uint32_t a[2][4];
            #pragma unroll
            for (int mt = 0; mt < 2; mt++) {
                uint32_t arow = (uint32_t)(wm * 32 + mt * 16) + a_rofs;
                ldsm_x4(a[mt][0], a[mt][1], a[mt][2], a[mt][3],
                        abase + arow * (APAD * 2) + (uint32_t)k16 * 32 + a_cofs);
            }
            #pragma unroll
            for (int np = 0; np < 4; np++) {   // ntile pair -> ntiles 2np, 2np+1
                uint32_t b0, b1, b2, b3;
                uint32_t brow = (uint32_t)(wn * 64 + np * 16) + b_rofs;
                ldsm_x4(b0, b1, b2, b3,
                        bbase + brow * (APAD * 2) + (uint32_t)k16 * 32 + b_cofs);
                #pragma unroll
                for (int mt = 0; mt < 2; mt++) {
                    mma_bf16(c[mt][2 * np],     a[mt][0], a[mt][1], a[mt][2], a[mt][3], b0, b1);
                    mma_bf16(c[mt][2 * np + 1], a[mt][0], a[mt][1], a[mt][2], a[mt][3], b2, b3);
                }
            }
        }
    }

    // ---- epilogue: n 0-127 -> g_xl, n 128-255 -> g_xr ----
    float* dstp = (wn >= 2) ? g_xr : g_xl;
    const int ncol0 = (wn & 1) * 64 + (lane & 3) * 2;
    #pragma unroll
    for (int mt = 0; mt < 2; mt++) {
        const int gr0 = row0 + wm * 32 + mt * 16 + (lane >> 2);
        #pragma unroll
        for (int t = 0; t < 8; t++) {
            int col = ncol0 + t * 8;
            if (gr0 < N)
                *reinterpret_cast<float2*>(&dstp[(size_t)gr0 * 128 + col]) =
                    make_float2(c[mt][t][0], c[mt][t][1]);
            if (gr0 + 8 < N)
                *reinterpret_cast<float2*>(&dstp[(size_t)(gr0 + 8) * 128 + col]) =
                    make_float2(c[mt][t][2], c[mt][t][3]);
        }
    }
}

// ================= catt: per-node per-head cl[n][h] = dot(xl[n], att_h) =================
// One warp per node; streaming L2 reads of g_xl (~10us).
__global__ void __launch_bounds__(256) calc_cl(const float* __restrict__ att) {
    int wid  = (blockIdx.x * blockDim.x + threadIdx.x) >> 5;
    int lane = threadIdx.x & 31;
    if (wid >= N) return;
    float4 v  = reinterpret_cast<const float4*>(g_xl)[(size_t)wid * 32 + lane];
    float4 at = __ldg(reinterpret_cast<const float4*>(att) + lane);
    float p = v.x * at.x + v.y * at.y + v.z * at.z + v.w * at.w;
    p += __shfl_xor_sync(0xffffffffu, p, 1);
    p += __shfl_xor_sync(0xffffffffu, p, 2);
    p += __shfl_xor_sync(0xffffffffu, p, 4);
    if ((lane & 7) == 0) g_cl[(size_t)wid * 4 + (lane >> 3)] = p;
}

// ================= fused node kernel: decomposed leaky-dot, no-max softmax =================
// logit = 0.6*(cl[src]+cr[dst]) + 0.4*sum_c |xl+xr|*att  (leaky = 0.6v + 0.4|v|).
// cr computed once per warp from register-resident xr. |.| is a free operand modifier.
__global__ void __launch_bounds__(256) node_fused(const float* __restrict__ att,
                                                  const float* __restrict__ b,
                                                  float* __restrict__ out,
                                                  int last) {
    int wid  = (blockIdx.x * blockDim.x + threadIdx.x) >> 5;
    int lane = threadIdx.x & 31;
    if (wid >= N) return;
    const int node = wid;
    const int hsel = lane >> 3;

    const float4* xl4p = reinterpret_cast<const float4*>(g_xl);
    const float4* xr4p = reinterpret_cast<const float4*>(g_xr);

    float4 xr = xr4p[(size_t)node * 32 + lane];
    float4 at = __ldg(reinterpret_cast<const float4*>(att) + lane);

    // cr for this node's head (all lanes in an 8-group end with the group sum)
    float crh;
    {
        float p = xr.x * at.x + xr.y * at.y + xr.z * at.z + xr.w * at.w;
        p += __shfl_xor_sync(0xffffffffu, p, 1);
        p += __shfl_xor_sync(0xffffffffu, p, 2);
        p += __shfl_xor_sync(0xffffffffu, p, 4);
        crh = p;
    }

    const int i0 = g_rowptr[node];
    const int i1 = g_rowptr[node + 1];     // index i1 itself = self loop

    float den = 0.f;
    float a0 = 0.f, a1 = 0.f, a2 = 0.f, a3 = 0.f;

    for (int base = i0; base <= i1; base += 4) {
        int sj[4];
        #pragma unroll
        for (int j = 0; j < 4; j++) {
            int idx = base + j;
            sj[j] = (idx < i1) ? __ldg(&g_col[idx]) : node;
        }
        float4 xlj[4];
        #pragma unroll
        for (int j = 0; j < 4; j++)
            xlj[j] = xl4p[(size_t)sj[j] * 32 + lane];
        float clj[4];
        #pragma unroll
        for (int j = 0; j < 4; j++)
            clj[j] = __ldg(&g_cl[(size_t)sj[j] * 4 + hsel]);

        float pj[4];
        #pragma unroll
        for (int j = 0; j < 4; j++) {
            float v0 = xlj[j].x + xr.x;
            float v1 = xlj[j].y + xr.y;
            float v2 = xlj[j].z + xr.z;
            float v3 = xlj[j].w + xr.w;
            pj[j] = fmaf(fabsf(v0), at.x,
                    fmaf(fabsf(v1), at.y,
                    fmaf(fabsf(v2), at.z, fabsf(v3) * at.w)));
        }
        #pragma unroll
        for (int o = 1; o <= 4; o <<= 1) {
            #pragma unroll
            for (int j = 0; j < 4; j++)
                pj[j] += __shfl_xor_sync(0xffffffffu, pj[j], o);
        }
        #pragma unroll
        for (int j = 0; j < 4; j++) {
            float lg = fmaf(0.4f, pj[j], 0.6f * (clj[j] + crh));
            float w = (base + j <= i1) ? __expf(fminf(lg, 60.f)) : 0.f;
            a0 = fmaf(w, xlj[j].x, a0);
            a1 = fmaf(w, xlj[j].y, a1);
            a2 = fmaf(w, xlj[j].z, a2);
            a3 = fmaf(w, xlj[j].w, a3);
            den += w;
        }
    }

    float inv = 1.f / den;
    float t0 = a0 * inv, t1 = a1 * inv, t2 = a2 * inv, t3 = a3 * inv;

    if (!last) {
        float4 bb = __ldg(reinterpret_cast<const float4*>(b) + lane);
        float4 o;
        o.x = fmaxf(t0 + bb.x, 0.f);
        o.y = fmaxf(t1 + bb.y, 0.f);
        o.z = fmaxf(t2 + bb.z, 0.f);
        o.w = fmaxf(t3 + bb.w, 0.f);
        reinterpret_cast<float4*>(out)[(size_t)node * 32 + lane] = o;
    } else {
        #pragma unroll
        for (int o = 8; o <= 16; o <<= 1) {
            t0 += __shfl_xor_sync(0xffffffffu, t0, o);
            t1 += __shfl_xor_sync(0xffffffffu, t1, o);
            t2 += __shfl_xor_sync(0xffffffffu, t2, o);
            t3 += __shfl_xor_sync(0xffffffffu, t3, o);
        }
        if (lane < 8) {
            float4 bb = __ldg(reinterpret_cast<const float4*>(b) + lane);
            float4 o;
            o.x = fmaxf(0.25f * t0 + bb.x, 0.f);
            o.y = fmaxf(0.25f * t1 + bb.y, 0.f);
            o.z = fmaxf(0.25f * t2 + bb.z, 0.f);
            o.w = fmaxf(0.25f * t3 + bb.w, 0.f);
            reinterpret_cast<float4*>(out)[(size_t)node * 8 + lane] = o;
        }
    }
}

// ================= host driver =================
static void run_layer(const float* xin, const float* Wl, const float* Wr,
                      const float* att, const float* b, float* out, int last) {
    wprep<<<dim3(4, 4, 2), dim3(32, 32)>>>(Wl, Wr);
    mma_gemm<<<(N + 63) / 64, 256, SM_GEMM_TOTAL>>>(xin);
    calc_cl<<<(N + 7) / 8, 256>>>(att);
    node_fused<<<(N + 7) / 8, 256>>>(att, b, out, last);
}

extern "C" void kernel_launch(void* const* d_in, const int* in_sizes, int n_in,
                              void* d_out, int out_size) {
    const float* x    = (const float*)d_in[0];
    const int*   ei   = (const int*)d_in[1];
    const float* W1l  = (const float*)d_in[2];
    const float* W1r  = (const float*)d_in[3];
    const float* att1 = (const float*)d_in[4];
    const float* b1   = (const float*)d_in[5];
    const float* W2l  = (const float*)d_in[6];
    const float* W2r  = (const float*)d_in[7];
    const float* att2 = (const float*)d_in[8];
    const float* b2   = (const float*)d_in[9];
    const float* W3l  = (const float*)d_in[10];
    const float* W3r  = (const float*)d_in[11];
    const float* att3 = (const float*)d_in[12];
    const float* b3   = (const float*)d_in[13];

    const int* src = ei;
    const int* dst = ei + E_IN;

    cudaFuncSetAttribute(mma_gemm, cudaFuncAttributeMaxDynamicSharedMemorySize, SM_GEMM_TOTAL);

    // CSR build (edges identical across layers)
    zero_deg<<<(N + 255) / 256, 256>>>();
    hist_dst<<<(E_IN + 255) / 256, 256>>>(dst);
    scan_deg<<<1, 1024>>>();
    scatter_csr<<<(E_IN + 255) / 256, 256>>>(src, dst);

    float *h1, *h2;
    cudaGetSymbolAddress((void**)&h1, g_h1);
    cudaGetSymbolAddress((void**)&h2, g_h2);

    run_layer(x,  W1l, W1r, att1, b1, h1,            0);
    run_layer(h1, W2l, W2r, att2, b2, h2,            0);
    run_layer(h2, W3l, W3r, att3, b3, (float*)d_out, 1);
}

// round 13
// speedup vs baseline: 1.1844x; 1.1844x over previous
#include <cuda_runtime.h>
#include <cuda_bf16.h>
#include <cstddef>
#include <cstdint>
#include <math_constants.h>

constexpr int N     = 100000;
constexpr int E_IN  = 1600000;
constexpr int HC    = 128;   // H*C, also F_IN
constexpr float SLOPE = 0.2f;

// ---------------- scratch ----------------
__device__ float g_xl[(size_t)N * HC];
__device__ float g_xr[(size_t)N * HC];
__device__ float g_h1[(size_t)N * HC];
__device__ float g_h2[(size_t)N * HC];
__device__ int   g_deg[N];
__device__ int   g_cursor[N];
__device__ int   g_rowptr[N + 1];
__device__ int   g_col[E_IN];
// Per-layer W transposed + bf16 hi/lo split: rows 0-127 = Wl^T, 128-255 = Wr^T
__device__ uint4 g_BT_hi[3][256 * 128 / 8];
__device__ uint4 g_BT_lo[3][256 * 128 / 8];

__device__ __forceinline__ uint32_t smem_u32(const void* p) {
    uint32_t a;
    asm("{ .reg .u64 t; cvta.to.shared.u64 t, %1; cvt.u32.u64 %0, t; }" : "=r"(a) : "l"(p));
    return a;
}
__device__ __forceinline__ unsigned pkbf(__nv_bfloat16 a, __nv_bfloat16 b) {
    __nv_bfloat162 t(a, b);
    return *reinterpret_cast<unsigned*>(&t);
}
__device__ __forceinline__ void ldsm_x4(uint32_t& r0, uint32_t& r1, uint32_t& r2, uint32_t& r3,
                                        uint32_t addr) {
    asm volatile("ldmatrix.sync.aligned.m8n8.x4.shared.b16 {%0,%1,%2,%3}, [%4];"
                 : "=r"(r0), "=r"(r1), "=r"(r2), "=r"(r3) : "r"(addr));
}
__device__ __forceinline__ void mma_bf16(float* c, uint32_t a0, uint32_t a1, uint32_t a2,
                                         uint32_t a3, uint32_t b0, uint32_t b1) {
    asm volatile("mma.sync.aligned.m16n8k16.row.col.f32.bf16.bf16.f32 "
                 "{%0,%1,%2,%3}, {%4,%5,%6,%7}, {%8,%9}, {%0,%1,%2,%3};"
                 : "+f"(c[0]), "+f"(c[1]), "+f"(c[2]), "+f"(c[3])
                 : "r"(a0), "r"(a1), "r"(a2), "r"(a3), "r"(b0), "r"(b1));
}

// ================= CSR build (once per launch) =================
__global__ void zero_deg() {
    int i = blockIdx.x * blockDim.x + threadIdx.x;
    if (i < N) g_deg[i] = 0;
}
__global__ void hist_dst(const int* __restrict__ dst) {
    int e = blockIdx.x * blockDim.x + threadIdx.x;
    if (e < E_IN) atomicAdd(&g_deg[dst[e]], 1);
}
__global__ void __launch_bounds__(1024) scan_deg() {
    __shared__ int sums[1024];
    const int CH = (N + 1023) / 1024;
    int t = threadIdx.x;
    int start = t * CH;
    int end   = start + CH < N ? start + CH : N;
    int s = 0;
    for (int i = start; i < end; i++) s += g_deg[i];
    sums[t] = s;
    __syncthreads();
    #pragma unroll
    for (int o = 1; o < 1024; o <<= 1) {
        int v = (t >= o) ? sums[t - o] : 0;
        __syncthreads();
        sums[t] += v;
        __syncthreads();
    }
    int run = sums[t] - s;
    for (int i = start; i < end; i++) {
        g_rowptr[i] = run;
        g_cursor[i] = run;
        run += g_deg[i];
    }
    if (t == 1023) g_rowptr[N] = E_IN;
}
__global__ void scatter_csr(const int* __restrict__ src, const int* __restrict__ dst) {
    int e = blockIdx.x * blockDim.x + threadIdx.x;
    if (e >= E_IN) return;
    int pos = atomicAdd(&g_cursor[dst[e]], 1);
    g_col[pos] = src[e];
}

// ================= W prep: transpose + bf16 hi/lo split (per layer) =================
__global__ void wprep(const float* __restrict__ Wl, const float* __restrict__ Wr, int layer) {
    __shared__ float t[32][33];
    const float* W = blockIdx.z ? Wr : Wl;
    int k0 = blockIdx.x * 32, n0 = blockIdx.y * 32;
    int tx = threadIdx.x, ty = threadIdx.y;
    t[ty][tx] = W[(k0 + ty) * HC + n0 + tx];
    __syncthreads();
    float v = t[tx][ty];
    __nv_bfloat16 h = __float2bfloat16_rn(v);
    float r = v - __bfloat162float(h);
    __nv_bfloat16 l = __float2bfloat16_rn(r);
    int n = n0 + ty + (int)blockIdx.z * 128;
    int k = k0 + tx;
    reinterpret_cast<__nv_bfloat16*>(g_BT_hi[layer])[n * 128 + k] = h;
    reinterpret_cast<__nv_bfloat16*>(g_BT_lo[layer])[n * 128 + k] = l;
}

// ================= mma.sync bf16 GEMM, 3-term split, both sides fused (R6 config) =================
// CTA: 256 thr = 2(m) x 4(n) warps; tile M64 x N256 (N 0-127 -> xl, 128-255 -> xr), K=128.
constexpr int APAD = 136;                          // bf16 elems per padded row (272 B)
constexpr int SM_A_HI = 0;
constexpr int SM_A_LO = SM_A_HI + 64 * APAD * 2;   // 17408
constexpr int SM_B_HI = SM_A_LO + 64 * APAD * 2;   // 34816
constexpr int SM_B_LO = SM_B_HI + 256 * APAD * 2;  // 104448
constexpr int SM_GEMM_TOTAL = SM_B_LO + 256 * APAD * 2;  // 174080 B

__global__ void __launch_bounds__(256, 1) mma_gemm(const float* __restrict__ X, int layer) {
    extern __shared__ char smem[];
    const uint32_t sb = smem_u32(smem);
    const int tid  = threadIdx.x;
    const int wid  = tid >> 5;
    const int lane = tid & 31;
    const int row0 = blockIdx.x * 64;

    // ---- stage A: 64 rows x 128 cols fp32 -> bf16 hi/lo (ONCE for both sides) ----
    const float4* X4 = reinterpret_cast<const float4*>(X);
    #pragma unroll
    for (int it = 0; it < 8; it++) {
        int idx = it * 256 + tid;           // 2048 float4 slots
        int r   = idx >> 5;
        int c4  = idx & 31;
        int g   = row0 + r;
        float4 f = (g < N) ? X4[(size_t)g * 32 + c4] : make_float4(0.f, 0.f, 0.f, 0.f);
        float e[4] = {f.x, f.y, f.z, f.w};
        __nv_bfloat16 h[4], l[4];
        #pragma unroll
        for (int i = 0; i < 4; i++) {
            h[i] = __float2bfloat16_rn(e[i]);
            l[i] = __float2bfloat16_rn(e[i] - __bfloat162float(h[i]));
        }
        uint2 hv = make_uint2(pkbf(h[0], h[1]), pkbf(h[2], h[3]));
        uint2 lv = make_uint2(pkbf(l[0], l[1]), pkbf(l[2], l[3]));
        uint32_t off = (uint32_t)(r * (APAD * 2) + c4 * 8);
        *reinterpret_cast<uint2*>(smem + SM_A_HI + off) = hv;
        *reinterpret_cast<uint2*>(smem + SM_A_LO + off) = lv;
    }
    // ---- stage B: 256 rows(n = [Wl^T; Wr^T]) x 128 cols(k) bf16 ----
    const uint4* bth = g_BT_hi[layer];
    const uint4* btl = g_BT_lo[layer];
    #pragma unroll
    for (int it = 0; it < 16; it++) {
        int idx = it * 256 + tid;           // 4096 uint4 slots
        int r   = idx >> 4;
        int q   = idx & 15;
        uint4 hv = bth[r * 16 + q];
        uint4 lv = btl[r * 16 + q];
        uint32_t off = (uint32_t)(r * (APAD * 2) + q * 16);
        *reinterpret_cast<uint4*>(smem + SM_B_HI + off) = hv;
        *reinterpret_cast<uint4*>(smem + SM_B_LO + off) = lv;
    }
    __syncthreads();

    const int wm = wid & 1;      // m-warp 0..1 -> rows wm*32 (two m16 tiles)
    const int wn = wid >> 1;     // n-warp 0..3 -> cols wn*64

    float c[2][8][4];
    #pragma unroll
    for (int mt = 0; mt < 2; mt++)
        #pragma unroll
        for (int t = 0; t < 8; t++)
            #pragma unroll
            for (int i = 0; i < 4; i++) c[mt][t][i] = 0.f;

    const uint32_t a_rofs = (uint32_t)(lane & 15);
    const uint32_t a_cofs = (uint32_t)((lane >> 4) * 16);          // bytes
    const uint32_t b_rofs = (uint32_t)((lane & 7) + ((lane & 16) >> 1));
    const uint32_t b_cofs = (uint32_t)(((lane >> 3) & 1) * 16);    // bytes

    #pragma unroll
    for (int term = 0; term < 3; term++) {
        const uint32_t abase = sb + ((term == 2) ? SM_A_LO : SM_A_HI);
        const uint32_t bbase = sb + ((term == 1) ? SM_B_LO : SM_B_HI);
        #pragma unroll
        for (int k16 = 0; k16 < 8; k16++) {
            uint32_t a[2][4];
            #pragma unroll
            for (int mt = 0; mt < 2; mt++) {
                uint32_t arow = (uint32_t)(wm * 32 + mt * 16) + a_rofs;
                ldsm_x4(a[mt][0], a[mt][1], a[mt][2], a[mt][3],
                        abase + arow * (APAD * 2) + (uint32_t)k16 * 32 + a_cofs);
            }
            #pragma unroll
            for (int np = 0; np < 4; np++) {   // ntile pair -> ntiles 2np, 2np+1
                uint32_t b0, b1, b2, b3;
                uint32_t brow = (uint32_t)(wn * 64 + np * 16) + b_rofs;
                ldsm_x4(b0, b1, b2, b3,
                        bbase + brow * (APAD * 2) + (uint32_t)k16 * 32 + b_cofs);
                #pragma unroll
                for (int mt = 0; mt < 2; mt++) {
                    mma_bf16(c[mt][2 * np],     a[mt][0], a[mt][1], a[mt][2], a[mt][3], b0, b1);
                    mma_bf16(c[mt][2 * np + 1], a[mt][0], a[mt][1], a[mt][2], a[mt][3], b2, b3);
                }
            }
        }
    }

    // ---- epilogue: n 0-127 -> g_xl, n 128-255 -> g_xr ----
    float* dstp = (wn >= 2) ? g_xr : g_xl;
    const int ncol0 = (wn & 1) * 64 + (lane & 3) * 2;
    #pragma unroll
    for (int mt = 0; mt < 2; mt++) {
        const int gr0 = row0 + wm * 32 + mt * 16 + (lane >> 2);
        #pragma unroll
        for (int t = 0; t < 8; t++) {
            int col = ncol0 + t * 8;
            if (gr0 < N)
                *reinterpret_cast<float2*>(&dstp[(size_t)gr0 * 128 + col]) =
                    make_float2(c[mt][t][0], c[mt][t][1]);
            if (gr0 + 8 < N)
                *reinterpret_cast<float2*>(&dstp[(size_t)(gr0 + 8) * 128 + col]) =
                    make_float2(c[mt][t][2], c[mt][t][3]);
        }
    }
}

// ================= fused node kernel (R6 exact): one warp per node =================
__global__ void __launch_bounds__(256) node_fused(const float* __restrict__ att,
                                                  const float* __restrict__ b,
                                                  float* __restrict__ out,
                                                  int last) {
    int wid  = (blockIdx.x * blockDim.x + threadIdx.x) >> 5;
    int lane = threadIdx.x & 31;
    if (wid >= N) return;
    const int node = wid;

    const float4* xl4p = reinterpret_cast<const float4*>(g_xl);
    const float4* xr4p = reinterpret_cast<const float4*>(g_xr);

    float4 xr = xr4p[(size_t)node * 32 + lane];
    float4 at = __ldg(reinterpret_cast<const float4*>(att) + lane);

    const int i0 = g_rowptr[node];
    const int i1 = g_rowptr[node + 1];     // index i1 itself = self loop

    float den = 0.f;
    float a0 = 0.f, a1 = 0.f, a2 = 0.f, a3 = 0.f;

    for (int base = i0; base <= i1; base += 4) {
        int sj[4];
        #pragma unroll
        for (int j = 0; j < 4; j++) {
            int idx = base + j;
            sj[j] = (idx < i1) ? __ldg(&g_col[idx]) : node;
        }
        float4 xlj[4];
        #pragma unroll
        for (int j = 0; j < 4; j++)
            xlj[j] = xl4p[(size_t)sj[j] * 32 + lane];
        float pj[4];
        #pragma unroll
        for (int j = 0; j < 4; j++) {
            float v0 = xlj[j].x + xr.x; v0 = (v0 > 0.f) ? v0 : SLOPE * v0;
            float v1 = xlj[j].y + xr.y; v1 = (v1 > 0.f) ? v1 : SLOPE * v1;
            float v2 = xlj[j].z + xr.z; v2 = (v2 > 0.f) ? v2 : SLOPE * v2;
            float v3 = xlj[j].w + xr.w; v3 = (v3 > 0.f) ? v3 : SLOPE * v3;
            pj[j] = v0 * at.x + v1 * at.y + v2 * at.z + v3 * at.w;
        }
        #pragma unroll
        for (int o = 1; o <= 4; o <<= 1) {
            #pragma unroll
            for (int j = 0; j < 4; j++)
                pj[j] += __shfl_xor_sync(0xffffffffu, pj[j], o);
        }
        #pragma unroll
        for (int j = 0; j < 4; j++) {
            float w = (base + j <= i1) ? __expf(fminf(pj[j], 60.f)) : 0.f;
            a0 = fmaf(w, xlj[j].x, a0);
            a1 = fmaf(w, xlj[j].y, a1);
            a2 = fmaf(w, xlj[j].z, a2);
            a3 = fmaf(w, xlj[j].w, a3);
            den += w;
        }
    }

    float inv = 1.f / den;
    float t0 = a0 * inv, t1 = a1 * inv, t2 = a2 * inv, t3 = a3 * inv;

    if (!last) {
        float4 bb = __ldg(reinterpret_cast<const float4*>(b) + lane);
        float4 o;
        o.x = fmaxf(t0 + bb.x, 0.f);
        o.y = fmaxf(t1 + bb.y, 0.f);
        o.z = fmaxf(t2 + bb.z, 0.f);
        o.w = fmaxf(t3 + bb.w, 0.f);
        reinterpret_cast<float4*>(out)[(size_t)node * 32 + lane] = o;
    } else {
        #pragma unroll
        for (int o = 8; o <= 16; o <<= 1) {
            t0 += __shfl_xor_sync(0xffffffffu, t0, o);
            t1 += __shfl_xor_sync(0xffffffffu, t1, o);
            t2 += __shfl_xor_sync(0xffffffffu, t2, o);
            t3 += __shfl_xor_sync(0xffffffffu, t3, o);
        }
        if (lane < 8) {
            float4 bb = __ldg(reinterpret_cast<const float4*>(b) + lane);
            float4 o;
            o.x = fmaxf(0.25f * t0 + bb.x, 0.f);
            o.y = fmaxf(0.25f * t1 + bb.y, 0.f);
            o.z = fmaxf(0.25f * t2 + bb.z, 0.f);
            o.w = fmaxf(0.25f * t3 + bb.w, 0.f);
            reinterpret_cast<float4*>(out)[(size_t)node * 8 + lane] = o;
        }
    }
}

// ================= host driver =================
extern "C" void kernel_launch(void* const* d_in, const int* in_sizes, int n_in,
                              void* d_out, int out_size) {
    const float* x    = (const float*)d_in[0];
    const int*   ei   = (const int*)d_in[1];
    const float* W1l  = (const float*)d_in[2];
    const float* W1r  = (const float*)d_in[3];
    const float* att1 = (const float*)d_in[4];
    const float* b1   = (const float*)d_in[5];
    const float* W2l  = (const float*)d_in[6];
    const float* W2r  = (const float*)d_in[7];
    const float* att2 = (const float*)d_in[8];
    const float* b2   = (const float*)d_in[9];
    const float* W3l  = (const float*)d_in[10];
    const float* W3r  = (const float*)d_in[11];
    const float* att3 = (const float*)d_in[12];
    const float* b3   = (const float*)d_in[13];

    const int* src = ei;
    const int* dst = ei + E_IN;

    // One-time resources (created during the uncaptured correctness call;
    // reused identically on every call -> same captured work each time).
    static cudaStream_t s2 = nullptr;
    static cudaEvent_t evFork = nullptr, evSide = nullptr;
    static bool attrSet = false;
    if (!s2) {
        cudaStreamCreateWithFlags(&s2, cudaStreamNonBlocking);
        cudaEventCreateWithFlags(&evFork, cudaEventDisableTiming);
        cudaEventCreateWithFlags(&evSide, cudaEventDisableTiming);
    }
    if (!attrSet) {
        cudaFuncSetAttribute(mma_gemm, cudaFuncAttributeMaxDynamicSharedMemorySize, SM_GEMM_TOTAL);
        attrSet = true;
    }

    cudaStream_t s0 = 0;   // harness capture stream (legacy default)

    float *h1, *h2;
    cudaGetSymbolAddress((void**)&h1, g_h1);
    cudaGetSymbolAddress((void**)&h2, g_h2);

    // ---- fork side stream: CSR build + wprep for layers 2,3 ----
    cudaEventRecord(evFork, s0);
    cudaStreamWaitEvent(s2, evFork, 0);
    zero_deg<<<(N + 255) / 256, 256, 0, s2>>>();
    hist_dst<<<(E_IN + 255) / 256, 256, 0, s2>>>(dst);
    scan_deg<<<1, 1024, 0, s2>>>();
    scatter_csr<<<(E_IN + 255) / 256, 256, 0, s2>>>(src, dst);
    wprep<<<dim3(4, 4, 2), dim3(32, 32), 0, s2>>>(W2l, W2r, 1);
    wprep<<<dim3(4, 4, 2), dim3(32, 32), 0, s2>>>(W3l, W3r, 2);
    cudaEventRecord(evSide, s2);

    // ---- main stream: layer-1 projections overlap the side work ----
    wprep<<<dim3(4, 4, 2), dim3(32, 32), 0, s0>>>(W1l, W1r, 0);
    mma_gemm<<<(N + 63) / 64, 256, SM_GEMM_TOTAL, s0>>>(x, 0);

    // ---- join: node_fused needs CSR (and later gemms need BT 1,2) ----
    cudaStreamWaitEvent(s0, evSide, 0);

    node_fused<<<(N + 7) / 8, 256, 0, s0>>>(att1, b1, h1, 0);
    mma_gemm<<<(N + 63) / 64, 256, SM_GEMM_TOTAL, s0>>>(h1, 1);
    node_fused<<<(N + 7) / 8, 256, 0, s0>>>(att2, b2, h2, 0);
    mma_gemm<<<(N + 63) / 64, 256, SM_GEMM_TOTAL, s0>>>(h2, 2);
    node_fused<<<(N + 7) / 8, 256, 0, s0>>>(att3, b3, (float*)d_out, 1);
}